// round 3
// baseline (speedup 1.0000x reference)
#include <cuda_runtime.h>
#include <cuda_bf16.h>
#include <cstdint>

// ---------------------------------------------------------------------------
// Compile-time Cl(4,1) Cayley structure tensors for the sandwich M X ~M.
// Generated as constexpr so all blade indices fold to compile-time constants
// -> register-resident multivectors, pure FFMA chain, no dynamic indexing.
// ---------------------------------------------------------------------------

struct Term { int a; int b; int c; float s; };
struct Tab80 { Term t[80]; };

__host__ __device__ constexpr int pc5(int x) {
    int c = 0;
    for (int i = 0; i < 6; i++) c += (x >> i) & 1;
    return c;
}

// blade product: basis blade a * basis blade b -> blade (a^b), sign
// metric: e1..e4 -> +1, e5 (bit 4, value 16) -> -1
__host__ __device__ constexpr int blade_mul_out(int a, int b) { return a ^ b; }

__host__ __device__ constexpr float blade_mul_sign(int a, int b) {
    int s = 0;
    int t = a >> 1;
    while (t) { s += pc5(t & b); t >>= 1; }
    float sign = (s & 1) ? -1.0f : 1.0f;
    if ((a & b) & 16) sign = -sign;  // e5^2 = -1
    return sign;
}

// T1: even[16] * g1[5] -> odd[16]   (M X)
__host__ __device__ constexpr Tab80 gen_T1() {
    Tab80 r{};
    int even[16] = {}, odd[16] = {};
    int ne = 0, no = 0;
    for (int b = 0; b < 32; b++) {
        if ((pc5(b) & 1) == 0) even[ne++] = b; else odd[no++] = b;
    }
    int g1[5] = {1, 2, 4, 8, 16};
    int oidx[32] = {};
    for (int i = 0; i < 16; i++) oidx[odd[i]] = i;
    int k = 0;
    for (int ie = 0; ie < 16; ie++) {
        for (int ip = 0; ip < 5; ip++) {
            int c = blade_mul_out(even[ie], g1[ip]);
            float s = blade_mul_sign(even[ie], g1[ip]);
            r.t[k].a = ie;        // versor index
            r.t[k].b = ip;        // point index
            r.t[k].c = oidx[c];   // odd output index
            r.t[k].s = s;
            k++;
        }
    }
    return r;
}

// T2: odd[16] * reverse(even[16]) -> grade-1[5]   ((M X) ~M, grade-1 part)
__host__ __device__ constexpr Tab80 gen_T2() {
    Tab80 r{};
    int even[16] = {}, odd[16] = {};
    int ne = 0, no = 0;
    for (int b = 0; b < 32; b++) {
        if ((pc5(b) & 1) == 0) even[ne++] = b; else odd[no++] = b;
    }
    int g1[5] = {1, 2, 4, 8, 16};
    int k = 0;
    for (int io = 0; io < 16; io++) {
        for (int ie = 0; ie < 16; ie++) {
            int c = blade_mul_out(odd[io], even[ie]);
            int gq = -1;
            for (int q = 0; q < 5; q++) if (g1[q] == c) gq = q;
            if (gq >= 0) {
                float s = blade_mul_sign(odd[io], even[ie]);
                int g = pc5(even[ie]);
                float rs = (((g * (g - 1) / 2) & 1) != 0) ? -1.0f : 1.0f;
                r.t[k].a = io;   // odd (mx) index
                r.t[k].b = ie;   // versor index
                r.t[k].c = gq;   // grade-1 output index
                r.t[k].s = s * rs;
                k++;
            }
        }
    }
    return r;
}

// ---------------------------------------------------------------------------
// Kernel: one thread per point.  HBM-bound streaming: 76B in, 12B out.
// ---------------------------------------------------------------------------
__global__ void __launch_bounds__(256)
cga_sandwich_kernel(const float* __restrict__ versor,
                    const float* __restrict__ x,
                    float* __restrict__ out,
                    int n)
{
    int i = blockIdx.x * blockDim.x + threadIdx.x;
    if (i >= n) return;

    // ---- load versor: 16 f32 via 4x float4 (64B, warp-contiguous) ----
    const float4* v4 = reinterpret_cast<const float4*>(versor) + (size_t)i * 4;
    float4 a0 = v4[0];
    float4 a1 = v4[1];
    float4 a2 = v4[2];
    float4 a3 = v4[3];
    float v[16] = {a0.x, a0.y, a0.z, a0.w,
                   a1.x, a1.y, a1.z, a1.w,
                   a2.x, a2.y, a2.z, a2.w,
                   a3.x, a3.y, a3.z, a3.w};

    // ---- load x (3 f32, warp covers contiguous 384B) ----
    const float* xp = x + (size_t)i * 3;
    float x0 = xp[0], x1 = xp[1], x2 = xp[2];

    // ---- CGA encode: P = (x, 0.5|x|^2 - 0.5, 0.5|x|^2 + 0.5) ----
    float hs = 0.5f * (x0 * x0 + x1 * x1 + x2 * x2);
    float p[5] = {x0, x1, x2, hs - 0.5f, hs + 0.5f};

    // ---- mx = M X (even * grade1 -> odd, 80 FFMA) ----
    constexpr Tab80 t1 = gen_T1();
    float mx[16] = {0, 0, 0, 0, 0, 0, 0, 0, 0, 0, 0, 0, 0, 0, 0, 0};
#pragma unroll
    for (int k = 0; k < 80; k++) {
        mx[t1.t[k].c] += t1.t[k].s * v[t1.t[k].a] * p[t1.t[k].b];
    }

    // ---- q = (M X) ~M, grade-1 part (80 FFMA) ----
    constexpr Tab80 t2 = gen_T2();
    float q[5] = {0, 0, 0, 0, 0};
#pragma unroll
    for (int k = 0; k < 80; k++) {
        q[t2.t[k].c] += t2.t[k].s * mx[t2.t[k].a] * v[t2.t[k].b];
    }

    // ---- CGA decode: xyz / (q_e5 - q_e4) ----
    float inv = 1.0f / (q[4] - q[3]);
    float* op = out + (size_t)i * 3;
    op[0] = q[0] * inv;
    op[1] = q[1] * inv;
    op[2] = q[2] * inv;
}

extern "C" void kernel_launch(void* const* d_in, const int* in_sizes, int n_in,
                              void* d_out, int out_size)
{
    const float* versor = (const float*)d_in[0];  // (N, 16) f32
    const float* x      = (const float*)d_in[1];  // (N, 3)  f32
    float* out          = (float*)d_out;          // (N, 3)  f32

    int n = in_sizes[0] / 16;
    int threads = 256;
    int blocks = (n + threads - 1) / threads;
    cga_sandwich_kernel<<<blocks, threads>>>(versor, x, out, n);
}